// round 7
// baseline (speedup 1.0000x reference)
#include <cuda_runtime.h>

#define TPB  128
#define NGPB 4        // groups (of 32 inputs) per block
#define CPT  2        // output columns per thread
#define NGY  64       // main-path grid.y; blockIdx.y == NGY runs the const path

typedef unsigned long long ull;

// Coefficient table: 34 entries per group, in PAIR order (entries 2p, 2p+1 form f32x2 pair p).
// Field value as float (after magic-subtract) == q * 2^s exactly; coeff = x[off] * KSCALE
// so fma gives q*x exactly.
__device__ const int KOFF[34] = {
    0,1, 2,3, 4,5, 6,7, 8,9, 10,10, 11,12, 13,14, 15,16, 17,18,
    19,20, 21,21, 22,23, 24,25, 26,27, 28,29, 30,31
};
__device__ const float KSCALE[34] = {
    0x1p0f, 0x1p-3f, 0x1p-6f, 0x1p-9f, 0x1p-12f, 0x1p-15f, 0x1p-18f,   // A fields j=0..6
    0x1p0f, 0x1p-3f, 0x1p-6f,                                          // B fields j=7..9 (r0>>21)
    0x1p-9f,                                                           // w10 lo (B bits 9-10)
    4.0f,                                                              // w10 hi (r1 bit 0)
    0x1p-1f, 0x1p-4f, 0x1p-7f, 0x1p-10f, 0x1p-13f, 0x1p-16f, 0x1p-19f, // C fields j=0..6
    0x1p0f, 0x1p-3f, 0x1p-6f,                                          // D fields j=7..9 (r1>>22)
    0x1p-9f,                                                           // w21 lo (D bit 9)
    2.0f,                                                              // w21 hi (r2 bits 0-1)
    0x1p-2f, 0x1p-5f, 0x1p-8f, 0x1p-11f, 0x1p-14f, 0x1p-17f, 0x1p-20f, // E fields j=0..6
    0x1p0f, 0x1p-3f, 0x1p-6f                                           // F fields j=7..9 (r2>>23)
};

// One packed step: two masked fields -> float pair via magic constant, subtract 2^23
// (exact), fma into packed accumulator. fma.rn.f32x2 = ONE instruction, two MACs.
#define PAIR(acc, va, ma, vb, mb, cp) do {                                        \
    ull _t;                                                                       \
    asm("mov.b64 %0, {%1,%2};" : "=l"(_t)                                         \
        : "r"(((va) & (ma)) | 0x4B000000u), "r"(((vb) & (mb)) | 0x4B000000u));    \
    asm("add.rn.f32x2 %0, %0, %1;" : "+l"(_t) : "l"(NEG64));                      \
    asm("fma.rn.f32x2 %0, %1, %2, %0;" : "+l"(acc) : "l"(_t), "l"(cp));           \
} while (0)

__device__ __forceinline__ void docol(ull& a0, ull& a1,
                                      unsigned A, unsigned C, unsigned E,
                                      const ull (&c)[17], ull NEG64)
{
    unsigned B = A >> 21, D = C >> 22, F = E >> 23;
    PAIR(a0, A, 0x00000007u, A, 0x00000038u, c[0]);
    PAIR(a1, A, 0x000001C0u, A, 0x00000E00u, c[1]);
    PAIR(a0, A, 0x00007000u, A, 0x00038000u, c[2]);
    PAIR(a1, A, 0x001C0000u, B, 0x00000007u, c[3]);
    PAIR(a0, B, 0x00000038u, B, 0x000001C0u, c[4]);
    PAIR(a1, B, 0x00000600u, C, 0x00000001u, c[5]);
    PAIR(a0, C, 0x0000000Eu, C, 0x00000070u, c[6]);
    PAIR(a1, C, 0x00000380u, C, 0x00001C00u, c[7]);
    PAIR(a0, C, 0x0000E000u, C, 0x00070000u, c[8]);
    PAIR(a1, C, 0x00380000u, D, 0x00000007u, c[9]);
    PAIR(a0, D, 0x00000038u, D, 0x000001C0u, c[10]);
    PAIR(a1, D, 0x00000200u, E, 0x00000003u, c[11]);
    PAIR(a0, E, 0x0000001Cu, E, 0x000000E0u, c[12]);
    PAIR(a1, E, 0x00000700u, E, 0x00003800u, c[13]);
    PAIR(a0, E, 0x0001C000u, E, 0x000E0000u, c[14]);
    PAIR(a1, E, 0x00700000u, F, 0x00000007u, c[15]);
    PAIR(a0, F, 0x00000038u, F, 0x000001C0u, c[16]);
}

// Single fused launch. Blocks with blockIdx.y < NGY: quantized-GEMV K-chunk into
// out via atomicAdd (R3 main-loop structure). Blocks with blockIdx.y == NGY:
// const path only: bias - zeros*sum(x) + oweight @ x[outlieridx], then return.
// out must be zeroed before launch (cudaMemsetAsync).
__global__ __launch_bounds__(TPB)
void k_fused(const float* __restrict__ x,
             const int*   __restrict__ qw,
             const float* __restrict__ scales,
             const float* __restrict__ zeros,
             const float* __restrict__ bias,
             const float* __restrict__ oweight,
             const int*   __restrict__ outlieridx,
             float* __restrict__ out,
             int OUTF, int INF, int NOUT)
{
    __shared__ __align__(16) float cs[NGPB * 36];
    __shared__ float wred[TPB / 32];
    __shared__ float xo[64];

    const int tid = threadIdx.x;
    const int colbase = blockIdx.x * (TPB * CPT) + tid * CPT;
    const int o0 = colbase, o1 = colbase + 1;

    if (blockIdx.y == NGY) {
        // ---- const-only path: never merges with the main path ----
        float s = 0.f;
        const float4* x4 = (const float4*)x;
        for (int i = tid; i < INF / 4; i += TPB) {
            float4 v = x4[i];
            s += (v.x + v.y) + (v.z + v.w);
        }
        #pragma unroll
        for (int d = 16; d > 0; d >>= 1) s += __shfl_xor_sync(0xFFFFFFFFu, s, d);
        if ((tid & 31) == 0) wred[tid >> 5] = s;
        if (tid < NOUT) xo[tid] = x[outlieridx[tid]];
        __syncthreads();

        const float sumx = wred[0] + wred[1] + wred[2] + wred[3];
        float base0 = bias[o0] - zeros[o0] * sumx;
        float base1 = bias[o1] - zeros[o1] * sumx;
        const float4* ow0 = (const float4*)(oweight + (size_t)o0 * NOUT);
        const float4* ow1 = (const float4*)(oweight + (size_t)o1 * NOUT);
        #pragma unroll 8
        for (int j = 0; j < NOUT / 4; ++j) {
            float4 u = ow0[j];
            float4 v = ow1[j];
            float q0 = xo[4 * j + 0], q1 = xo[4 * j + 1];
            float q2 = xo[4 * j + 2], q3 = xo[4 * j + 3];
            base0 = fmaf(u.x, q0, base0);
            base1 = fmaf(v.x, q0, base1);
            base0 = fmaf(u.y, q1, base0);
            base1 = fmaf(v.y, q1, base1);
            base0 = fmaf(u.z, q2, base0);
            base1 = fmaf(v.z, q2, base1);
            base0 = fmaf(u.w, q3, base0);
            base1 = fmaf(v.w, q3, base1);
        }
        atomicAdd(&out[o0], base0);
        atomicAdd(&out[o1], base1);
        return;
    }

    // ---- main path (R3 k_main structure) ----
    const int gbase = blockIdx.y * NGPB;

    for (int idx = tid; idx < NGPB * 34; idx += TPB) {
        int g = idx / 34, k = idx - g * 34;
        cs[g * 36 + k] = x[(gbase + g) * 32 + KOFF[k]] * KSCALE[k];
    }
    __syncthreads();

    const ull NEG64 = 0xCB000000CB000000ull;  // packed {-2^23, -2^23}
    const int rowstride2 = OUTF / 2;          // int2 stride between qweight rows

    ull a00 = 0ull, a01 = 0ull, a10 = 0ull, a11 = 0ull;

    const int2* row = (const int2*)(qw + (long)gbase * 3 * OUTF + colbase);

    // prefetch group 0 weights
    int2 w0 = row[0];
    int2 w1 = row[rowstride2];
    int2 w2 = row[2 * rowstride2];

    #pragma unroll
    for (int g = 0; g < NGPB; ++g) {
        int2 n0, n1, n2;
        if (g + 1 < NGPB) {
            const int2* nrow = row + 3 * rowstride2;
            n0 = nrow[0];
            n1 = nrow[rowstride2];
            n2 = nrow[2 * rowstride2];
            row = nrow;
        }

        // hoist this group's 17 coefficient pairs into registers
        ull c[17];
        const ull* cp = (const ull*)&cs[g * 36];
        #pragma unroll
        for (int k = 0; k < 17; ++k) c[k] = cp[k];

        docol(a00, a01, (unsigned)w0.x, (unsigned)w1.x, (unsigned)w2.x, c, NEG64);
        docol(a10, a11, (unsigned)w0.y, (unsigned)w1.y, (unsigned)w2.y, c, NEG64);

        w0 = n0; w1 = n1; w2 = n2;
    }

    {
        float s0 = __uint_as_float((unsigned)a00) + __uint_as_float((unsigned)(a00 >> 32));
        float s1 = __uint_as_float((unsigned)a01) + __uint_as_float((unsigned)(a01 >> 32));
        atomicAdd(&out[o0], scales[o0] * (s0 + s1));
    }
    {
        float s0 = __uint_as_float((unsigned)a10) + __uint_as_float((unsigned)(a10 >> 32));
        float s1 = __uint_as_float((unsigned)a11) + __uint_as_float((unsigned)(a11 >> 32));
        atomicAdd(&out[o1], scales[o1] * (s0 + s1));
    }
}

extern "C" void kernel_launch(void* const* d_in, const int* in_sizes, int n_in,
                              void* d_out, int out_size)
{
    const float* x      = (const float*)d_in[0];
    const int*   qw     = (const int*)  d_in[1];
    const float* scales = (const float*)d_in[2];
    const float* zeros  = (const float*)d_in[3];
    const float* bias   = (const float*)d_in[4];
    const float* ow     = (const float*)d_in[5];
    const int*   oidx   = (const int*)  d_in[6];
    float* out = (float*)d_out;

    const int INF  = in_sizes[0];          // 8192
    const int OUTF = in_sizes[2];          // 8192
    const int NOUT = in_sizes[6];          // 64
    (void)INF;

    cudaMemsetAsync(out, 0, (size_t)out_size * sizeof(float));

    dim3 grid(OUTF / (TPB * CPT), NGY + 1);  // (32, 65): 2048 main + 32 const blocks
    k_fused<<<grid, TPB>>>(x, qw, scales, zeros, bias, ow, oidx, out,
                           OUTF, INF, NOUT);
}

// round 8
// speedup vs baseline: 1.0152x; 1.0152x over previous
#include <cuda_runtime.h>

#define TPB  128
#define NGPB 4        // groups (of 32 inputs) per block
#define CPT  2        // output columns per thread
#define NGY  64       // main-path grid.y; blockIdx.y == NGY runs the const path

typedef unsigned long long ull;

// Coefficient table: 34 entries per group, in PAIR order (entries 2p, 2p+1 form f32x2 pair p).
// Field value as float (after magic-subtract) == q * 2^s exactly; coeff = x[off] * KSCALE
// so fma gives q*x exactly.
__device__ const int KOFF[34] = {
    0,1, 2,3, 4,5, 6,7, 8,9, 10,10, 11,12, 13,14, 15,16, 17,18,
    19,20, 21,21, 22,23, 24,25, 26,27, 28,29, 30,31
};
__device__ const float KSCALE[34] = {
    0x1p0f, 0x1p-3f, 0x1p-6f, 0x1p-9f, 0x1p-12f, 0x1p-15f, 0x1p-18f,   // A fields j=0..6
    0x1p0f, 0x1p-3f, 0x1p-6f,                                          // B fields j=7..9 (r0>>21)
    0x1p-9f,                                                           // w10 lo (B bits 9-10)
    4.0f,                                                              // w10 hi (r1 bit 0)
    0x1p-1f, 0x1p-4f, 0x1p-7f, 0x1p-10f, 0x1p-13f, 0x1p-16f, 0x1p-19f, // C fields j=0..6
    0x1p0f, 0x1p-3f, 0x1p-6f,                                          // D fields j=7..9 (r1>>22)
    0x1p-9f,                                                           // w21 lo (D bit 9)
    2.0f,                                                              // w21 hi (r2 bits 0-1)
    0x1p-2f, 0x1p-5f, 0x1p-8f, 0x1p-11f, 0x1p-14f, 0x1p-17f, 0x1p-20f, // E fields j=0..6
    0x1p0f, 0x1p-3f, 0x1p-6f                                           // F fields j=7..9 (r2>>23)
};

// One packed step: two masked fields -> float pair via magic constant, subtract 2^23
// (exact), fma into packed accumulator. fma.rn.f32x2 = ONE instruction, two MACs.
#define PAIR(acc, va, ma, vb, mb, cp) do {                                        \
    ull _t;                                                                       \
    asm("mov.b64 %0, {%1,%2};" : "=l"(_t)                                         \
        : "r"(((va) & (ma)) | 0x4B000000u), "r"(((vb) & (mb)) | 0x4B000000u));    \
    asm("add.rn.f32x2 %0, %0, %1;" : "+l"(_t) : "l"(NEG64));                      \
    asm("fma.rn.f32x2 %0, %1, %2, %0;" : "+l"(acc) : "l"(_t), "l"(cp));           \
} while (0)

// Process one 32-input group for TWO columns. Coefficients read as 9 x LDS.128
// (ulonglong2); each vector's .x/.y feed consecutive pairs for both columns.
__device__ __forceinline__ void docol2(
    ull& a00, ull& a01, ull& a10, ull& a11,
    unsigned A0, unsigned C0, unsigned E0,
    unsigned A1, unsigned C1, unsigned E1,
    const ulonglong2* __restrict__ cp, ull NEG64)
{
    unsigned B0 = A0 >> 21, D0 = C0 >> 22, F0 = E0 >> 23;
    unsigned B1 = A1 >> 21, D1 = C1 >> 22, F1 = E1 >> 23;
    ulonglong2 v;
    v = cp[0];
    PAIR(a00, A0, 0x00000007u, A0, 0x00000038u, v.x);
    PAIR(a10, A1, 0x00000007u, A1, 0x00000038u, v.x);
    PAIR(a01, A0, 0x000001C0u, A0, 0x00000E00u, v.y);
    PAIR(a11, A1, 0x000001C0u, A1, 0x00000E00u, v.y);
    v = cp[1];
    PAIR(a00, A0, 0x00007000u, A0, 0x00038000u, v.x);
    PAIR(a10, A1, 0x00007000u, A1, 0x00038000u, v.x);
    PAIR(a01, A0, 0x001C0000u, B0, 0x00000007u, v.y);
    PAIR(a11, A1, 0x001C0000u, B1, 0x00000007u, v.y);
    v = cp[2];
    PAIR(a00, B0, 0x00000038u, B0, 0x000001C0u, v.x);
    PAIR(a10, B1, 0x00000038u, B1, 0x000001C0u, v.x);
    PAIR(a01, B0, 0x00000600u, C0, 0x00000001u, v.y);
    PAIR(a11, B1, 0x00000600u, C1, 0x00000001u, v.y);
    v = cp[3];
    PAIR(a00, C0, 0x0000000Eu, C0, 0x00000070u, v.x);
    PAIR(a10, C1, 0x0000000Eu, C1, 0x00000070u, v.x);
    PAIR(a01, C0, 0x00000380u, C0, 0x00001C00u, v.y);
    PAIR(a11, C1, 0x00000380u, C1, 0x00001C00u, v.y);
    v = cp[4];
    PAIR(a00, C0, 0x0000E000u, C0, 0x00070000u, v.x);
    PAIR(a10, C1, 0x0000E000u, C1, 0x00070000u, v.x);
    PAIR(a01, C0, 0x00380000u, D0, 0x00000007u, v.y);
    PAIR(a11, C1, 0x00380000u, D1, 0x00000007u, v.y);
    v = cp[5];
    PAIR(a00, D0, 0x00000038u, D0, 0x000001C0u, v.x);
    PAIR(a10, D1, 0x00000038u, D1, 0x000001C0u, v.x);
    PAIR(a01, D0, 0x00000200u, E0, 0x00000003u, v.y);
    PAIR(a11, D1, 0x00000200u, E1, 0x00000003u, v.y);
    v = cp[6];
    PAIR(a00, E0, 0x0000001Cu, E0, 0x000000E0u, v.x);
    PAIR(a10, E1, 0x0000001Cu, E1, 0x000000E0u, v.x);
    PAIR(a01, E0, 0x00000700u, E0, 0x00003800u, v.y);
    PAIR(a11, E1, 0x00000700u, E1, 0x00003800u, v.y);
    v = cp[7];
    PAIR(a00, E0, 0x0001C000u, E0, 0x000E0000u, v.x);
    PAIR(a10, E1, 0x0001C000u, E1, 0x000E0000u, v.x);
    PAIR(a01, E0, 0x00700000u, F0, 0x00000007u, v.y);
    PAIR(a11, E1, 0x00700000u, F1, 0x00000007u, v.y);
    v = cp[8];
    PAIR(a00, F0, 0x00000038u, F0, 0x000001C0u, v.x);
    PAIR(a10, F1, 0x00000038u, F1, 0x000001C0u, v.x);
}

// Single fused launch. blockIdx.y < NGY: quantized-GEMV K-chunk, all 12 weight
// LDGs issued up front (MLP=12) before the coefficient-table build hides them.
// blockIdx.y == NGY: const path (bias - zeros*sum(x) + oweight @ x_outlier).
// out must be zeroed before launch (cudaMemsetAsync).
__global__ __launch_bounds__(TPB, 10)
void k_fused(const float* __restrict__ x,
             const int*   __restrict__ qw,
             const float* __restrict__ scales,
             const float* __restrict__ zeros,
             const float* __restrict__ bias,
             const float* __restrict__ oweight,
             const int*   __restrict__ outlieridx,
             float* __restrict__ out,
             int OUTF, int INF, int NOUT)
{
    __shared__ __align__(16) float cs[NGPB * 36];
    __shared__ float wred[TPB / 32];
    __shared__ float xo[64];

    const int tid = threadIdx.x;
    const int colbase = blockIdx.x * (TPB * CPT) + tid * CPT;
    const int o0 = colbase, o1 = colbase + 1;

    if (blockIdx.y == NGY) {
        // ---- const-only path ----
        float s = 0.f;
        const float4* x4 = (const float4*)x;
        for (int i = tid; i < INF / 4; i += TPB) {
            float4 v = x4[i];
            s += (v.x + v.y) + (v.z + v.w);
        }
        #pragma unroll
        for (int d = 16; d > 0; d >>= 1) s += __shfl_xor_sync(0xFFFFFFFFu, s, d);
        if ((tid & 31) == 0) wred[tid >> 5] = s;
        if (tid < NOUT) xo[tid] = x[outlieridx[tid]];
        __syncthreads();

        const float sumx = wred[0] + wred[1] + wred[2] + wred[3];
        float base0 = bias[o0] - zeros[o0] * sumx;
        float base1 = bias[o1] - zeros[o1] * sumx;
        const float4* ow0 = (const float4*)(oweight + (size_t)o0 * NOUT);
        const float4* ow1 = (const float4*)(oweight + (size_t)o1 * NOUT);
        #pragma unroll 8
        for (int j = 0; j < NOUT / 4; ++j) {
            float4 u = ow0[j];
            float4 v = ow1[j];
            float q0 = xo[4 * j + 0], q1 = xo[4 * j + 1];
            float q2 = xo[4 * j + 2], q3 = xo[4 * j + 3];
            base0 = fmaf(u.x, q0, base0);
            base1 = fmaf(v.x, q0, base1);
            base0 = fmaf(u.y, q1, base0);
            base1 = fmaf(v.y, q1, base1);
            base0 = fmaf(u.z, q2, base0);
            base1 = fmaf(v.z, q2, base1);
            base0 = fmaf(u.w, q3, base0);
            base1 = fmaf(v.w, q3, base1);
        }
        atomicAdd(&out[o0], base0);
        atomicAdd(&out[o1], base1);
        return;
    }

    // ---- main path ----
    const int gbase = blockIdx.y * NGPB;
    const int rowstride2 = OUTF / 2;  // int2 stride between qweight rows

    // Issue ALL 12 weight loads first (MLP=12); latency hidden by table build.
    const int2* row = (const int2*)(qw + (long)gbase * 3 * OUTF + colbase);
    int2 w[NGPB][3];
    #pragma unroll
    for (int g = 0; g < NGPB; ++g) {
        #pragma unroll
        for (int r = 0; r < 3; ++r)
            w[g][r] = row[(3 * g + r) * (long)rowstride2];
    }

    // Build prescaled coefficient table for this K-chunk (pad entries zeroed).
    for (int idx = tid; idx < NGPB * 36; idx += TPB) {
        int g = idx / 36, k = idx - g * 36;
        float v = 0.f;
        if (k < 34) v = x[(gbase + g) * 32 + KOFF[k]] * KSCALE[k];
        cs[idx] = v;
    }
    __syncthreads();

    const ull NEG64 = 0xCB000000CB000000ull;  // packed {-2^23, -2^23}

    ull a00 = 0ull, a01 = 0ull, a10 = 0ull, a11 = 0ull;

    #pragma unroll
    for (int g = 0; g < NGPB; ++g) {
        const ulonglong2* cp = (const ulonglong2*)&cs[g * 36];
        docol2(a00, a01, a10, a11,
               (unsigned)w[g][0].x, (unsigned)w[g][1].x, (unsigned)w[g][2].x,
               (unsigned)w[g][0].y, (unsigned)w[g][1].y, (unsigned)w[g][2].y,
               cp, NEG64);
    }

    {
        float s0 = __uint_as_float((unsigned)a00) + __uint_as_float((unsigned)(a00 >> 32));
        float s1 = __uint_as_float((unsigned)a01) + __uint_as_float((unsigned)(a01 >> 32));
        atomicAdd(&out[o0], scales[o0] * (s0 + s1));
    }
    {
        float s0 = __uint_as_float((unsigned)a10) + __uint_as_float((unsigned)(a10 >> 32));
        float s1 = __uint_as_float((unsigned)a11) + __uint_as_float((unsigned)(a11 >> 32));
        atomicAdd(&out[o1], scales[o1] * (s0 + s1));
    }
}

extern "C" void kernel_launch(void* const* d_in, const int* in_sizes, int n_in,
                              void* d_out, int out_size)
{
    const float* x      = (const float*)d_in[0];
    const int*   qw     = (const int*)  d_in[1];
    const float* scales = (const float*)d_in[2];
    const float* zeros  = (const float*)d_in[3];
    const float* bias   = (const float*)d_in[4];
    const float* ow     = (const float*)d_in[5];
    const int*   oidx   = (const int*)  d_in[6];
    float* out = (float*)d_out;

    const int INF  = in_sizes[0];          // 8192
    const int OUTF = in_sizes[2];          // 8192
    const int NOUT = in_sizes[6];          // 64

    cudaMemsetAsync(out, 0, (size_t)out_size * sizeof(float));

    dim3 grid(OUTF / (TPB * CPT), NGY + 1);  // (32, 65): 2048 main + 32 const blocks
    k_fused<<<grid, TPB>>>(x, qw, scales, zeros, bias, ow, oidx, out,
                           OUTF, INF, NOUT);
}

// round 9
// speedup vs baseline: 1.2739x; 1.2548x over previous
#include <cuda_runtime.h>

#define TPB  128
#define NGPB 8        // groups (of 32 inputs) per block
#define CPT  2        // output columns per thread
#define NGY  32       // main-path grid.y; blockIdx.y == NGY runs the const path

typedef unsigned long long ull;

// 34 coefficient entries per group, stored in PAIR order (2p, 2p+1 form the f32x2
// pair for piece-pair p). Piece value (masked bits, after magic-subtract) ==
// q * 2^s exactly; coeff = x[off] * KSCALE2 so fma gives q*x exactly.
__device__ const int KOFF2[34] = {
    0,1,  2,3,  4,5,  6,16,  7,8,  9,10,  10,11,  12,13,  14,15,
    17,18,  19,20,  21,31,  21,22,  23,24,  25,26,  27,28,  29,30
};
__device__ const float KSCALE2[34] = {
    0x1p0f, 0x1p-3f,   0x1p-6f, 0x1p-9f,   0x1p-12f, 0x1p-15f,
    0x1p-18f, 0x1p-16f,  // mixed pair M1: A-field j6 (bit18), C-field j16 (bit16)
    0x1p-9f, 0x1p-12f,   0x1p-15f, 0x1p-18f,   // A>>12 fields (orig bits 21,24,27,30)
    4.0f, 0x1p-1f,       0x1p-4f, 0x1p-7f,   0x1p-10f, 0x1p-13f,
    0x1p-7f, 0x1p-10f,   0x1p-13f, 0x1p-16f,    // C>>12 fields (orig 19,22,25,28)
    0x1p-19f, 0x1p-17f,  // mixed pair M2: w21lo (C bit31>>12), E-field j31 (bit29>>12)
    2.0f, 0x1p-2f,       0x1p-5f, 0x1p-8f,   0x1p-11f, 0x1p-14f,
    0x1p-17f, 0x1p-20f,  0x1p-11f, 0x1p-14f     // E direct tail + E>>12 fields
};

// 64-bit mask with the fp32 magic exponent (2^23) kept in both halves.
#define MK64(mlo, mhi) ((((ull)((mhi) | 0x4B000000u)) << 32) | (ull)((mlo) | 0x4B000000u))

// One piece-pair: 64-bit AND isolates two magic-biased fields directly into an
// aligned register pair (2 LOP3, no MOV), exact packed subtract of 2^23, packed fma.
#define PPAIR(acc, word, mlo, mhi, cpv) do {                                  \
    ull _t = (word) & MK64(mlo, mhi);                                         \
    asm("add.rn.f32x2 %0, %0, %1;" : "+l"(_t) : "l"(NEG64));                  \
    asm("fma.rn.f32x2 %0, %1, %2, %0;" : "+l"(acc) : "l"(_t), "l"(cpv));      \
} while (0)

// One 32-input group for ONE column: 17 piece-pairs into 2 packed accumulators.
__device__ __forceinline__ void docol(ull& aa, ull& ab,
                                      unsigned A, unsigned C, unsigned E,
                                      const ull* __restrict__ cp, ull NEG64)
{
    // magic-biased direct words (fields ending <= bit 22) and >>12 shifted words
    unsigned Am = (A & 0x007FFFFFu) | 0x4B000000u;
    unsigned As = ((A >> 12) & 0x000FFFFFu) | 0x4B000000u;
    unsigned Cm = (C & 0x007FFFFFu) | 0x4B000000u;
    unsigned Cs = ((C >> 12) & 0x000FFFFFu) | 0x4B000000u;
    unsigned Em = (E & 0x007FFFFFu) | 0x4B000000u;
    unsigned Es = ((E >> 12) & 0x000FFFFFu) | 0x4B000000u;

    ull AmW = ((ull)Am << 32) | Am;
    ull AsW = ((ull)As << 32) | As;
    ull CmW = ((ull)Cm << 32) | Cm;
    ull CsW = ((ull)Cs << 32) | Cs;
    ull EmW = ((ull)Em << 32) | Em;
    ull EsW = ((ull)Es << 32) | Es;
    ull X1  = ((ull)Cm << 32) | Am;   // mixed: odd A piece + odd C piece
    ull X2  = ((ull)Es << 32) | Cs;   // mixed: w21lo + odd E piece

    PPAIR(aa, AmW, 0x00000007u, 0x00000038u, cp[0]);   // j0, j1
    PPAIR(ab, AmW, 0x000001C0u, 0x00000E00u, cp[1]);   // j2, j3
    PPAIR(aa, AmW, 0x00007000u, 0x00038000u, cp[2]);   // j4, j5
    PPAIR(ab, X1,  0x001C0000u, 0x00070000u, cp[3]);   // j6, j16
    PPAIR(aa, AsW, 0x00000E00u, 0x00007000u, cp[4]);   // j7(21>>12), j8(24>>12)
    PPAIR(ab, AsW, 0x00038000u, 0x000C0000u, cp[5]);   // j9(27>>12), w10lo(30>>12)
    PPAIR(aa, CmW, 0x00000001u, 0x0000000Eu, cp[6]);   // w10hi, j11
    PPAIR(ab, CmW, 0x00000070u, 0x00000380u, cp[7]);   // j12, j13
    PPAIR(aa, CmW, 0x00001C00u, 0x0000E000u, cp[8]);   // j14, j15
    PPAIR(ab, CsW, 0x00000380u, 0x00001C00u, cp[9]);   // j17(19>>12), j18(22>>12)
    PPAIR(aa, CsW, 0x0000E000u, 0x00070000u, cp[10]);  // j19(25>>12), j20(28>>12)
    PPAIR(ab, X2,  0x00080000u, 0x000E0000u, cp[11]);  // w21lo(31>>12), j31(29>>12)
    PPAIR(aa, EmW, 0x00000003u, 0x0000001Cu, cp[12]);  // w21hi, j22
    PPAIR(ab, EmW, 0x000000E0u, 0x00000700u, cp[13]);  // j23, j24
    PPAIR(aa, EmW, 0x00003800u, 0x0001C000u, cp[14]);  // j25, j26
    PPAIR(ab, EmW, 0x000E0000u, 0x00700000u, cp[15]);  // j27, j28
    PPAIR(aa, EsW, 0x00003800u, 0x0001C000u, cp[16]);  // j29(23>>12), j30(26>>12)
}

// Single fused launch. blockIdx.y < NGY: quantized-GEMV K-chunk (8 groups, rolling
// 4-group weight prefetch). blockIdx.y == NGY: const path. out pre-zeroed.
__global__ __launch_bounds__(TPB, 8)
void k_fused(const float* __restrict__ x,
             const int*   __restrict__ qw,
             const float* __restrict__ scales,
             const float* __restrict__ zeros,
             const float* __restrict__ bias,
             const float* __restrict__ oweight,
             const int*   __restrict__ outlieridx,
             float* __restrict__ out,
             int OUTF, int INF, int NOUT)
{
    __shared__ __align__(16) float cs[NGPB * 36];
    __shared__ float wred[TPB / 32];
    __shared__ float xo[64];

    const int tid = threadIdx.x;
    const int colbase = blockIdx.x * (TPB * CPT) + tid * CPT;
    const int o0 = colbase, o1 = colbase + 1;

    if (blockIdx.y == NGY) {
        // ---- const-only path ----
        float s = 0.f;
        const float4* x4 = (const float4*)x;
        for (int i = tid; i < INF / 4; i += TPB) {
            float4 v = x4[i];
            s += (v.x + v.y) + (v.z + v.w);
        }
        #pragma unroll
        for (int d = 16; d > 0; d >>= 1) s += __shfl_xor_sync(0xFFFFFFFFu, s, d);
        if ((tid & 31) == 0) wred[tid >> 5] = s;
        if (tid < NOUT) xo[tid] = x[outlieridx[tid]];
        __syncthreads();

        const float sumx = wred[0] + wred[1] + wred[2] + wred[3];
        float base0 = bias[o0] - zeros[o0] * sumx;
        float base1 = bias[o1] - zeros[o1] * sumx;
        const float4* ow0 = (const float4*)(oweight + (size_t)o0 * NOUT);
        const float4* ow1 = (const float4*)(oweight + (size_t)o1 * NOUT);
        #pragma unroll 8
        for (int j = 0; j < NOUT / 4; ++j) {
            float4 u = ow0[j];
            float4 v = ow1[j];
            float q0 = xo[4 * j + 0], q1 = xo[4 * j + 1];
            float q2 = xo[4 * j + 2], q3 = xo[4 * j + 3];
            base0 = fmaf(u.x, q0, base0);
            base1 = fmaf(v.x, q0, base1);
            base0 = fmaf(u.y, q1, base0);
            base1 = fmaf(v.y, q1, base1);
            base0 = fmaf(u.z, q2, base0);
            base1 = fmaf(v.z, q2, base1);
            base0 = fmaf(u.w, q3, base0);
            base1 = fmaf(v.w, q3, base1);
        }
        atomicAdd(&out[o0], base0);
        atomicAdd(&out[o1], base1);
        return;
    }

    // ---- main path ----
    const int gbase = blockIdx.y * NGPB;
    const long stride = OUTF / 2;  // ull stride between qweight rows

    // Column-pair pointer: each ull load = {col0, col1} of one packed row.
    const ull* colptr = (const ull*)qw + (long)gbase * 3 * stride + (colbase >> 1);

    // Rolling ring: preload groups 0..3 (MLP=12 up front, refilled as we go).
    ull rw[4][3];
    #pragma unroll
    for (int g = 0; g < 4; ++g) {
        #pragma unroll
        for (int r = 0; r < 3; ++r)
            rw[g][r] = colptr[(3 * g + r) * stride];
    }

    // Build prescaled coefficient table (34 entries per group, pair order).
    for (int idx = tid; idx < NGPB * 34; idx += TPB) {
        int g = idx / 34, k = idx - g * 34;
        cs[g * 36 + k] = x[(gbase + g) * 32 + KOFF2[k]] * KSCALE2[k];
    }
    __syncthreads();

    const ull NEG64 = 0xCB000000CB000000ull;  // packed {-2^23, -2^23}

    ull a00 = 0ull, a01 = 0ull, a10 = 0ull, a11 = 0ull;

    #pragma unroll
    for (int g = 0; g < NGPB; ++g) {
        ull A = rw[g & 3][0], C = rw[g & 3][1], E = rw[g & 3][2];

        if (g + 4 < NGPB) {
            #pragma unroll
            for (int r = 0; r < 3; ++r)
                rw[g & 3][r] = colptr[(3 * (g + 4) + r) * stride];
        }

        const ull* cp = (const ull*)&cs[g * 36];
        docol(a00, a01, (unsigned)A, (unsigned)C, (unsigned)E, cp, NEG64);
        docol(a10, a11, (unsigned)(A >> 32), (unsigned)(C >> 32), (unsigned)(E >> 32),
              cp, NEG64);
    }

    {
        float s0 = __uint_as_float((unsigned)a00) + __uint_as_float((unsigned)(a00 >> 32));
        float s1 = __uint_as_float((unsigned)a01) + __uint_as_float((unsigned)(a01 >> 32));
        atomicAdd(&out[o0], scales[o0] * (s0 + s1));
    }
    {
        float s0 = __uint_as_float((unsigned)a10) + __uint_as_float((unsigned)(a10 >> 32));
        float s1 = __uint_as_float((unsigned)a11) + __uint_as_float((unsigned)(a11 >> 32));
        atomicAdd(&out[o1], scales[o1] * (s0 + s1));
    }
}

extern "C" void kernel_launch(void* const* d_in, const int* in_sizes, int n_in,
                              void* d_out, int out_size)
{
    const float* x      = (const float*)d_in[0];
    const int*   qw     = (const int*)  d_in[1];
    const float* scales = (const float*)d_in[2];
    const float* zeros  = (const float*)d_in[3];
    const float* bias   = (const float*)d_in[4];
    const float* ow     = (const float*)d_in[5];
    const int*   oidx   = (const int*)  d_in[6];
    float* out = (float*)d_out;

    const int INF  = in_sizes[0];          // 8192
    const int OUTF = in_sizes[2];          // 8192
    const int NOUT = in_sizes[6];          // 64

    cudaMemsetAsync(out, 0, (size_t)out_size * sizeof(float));

    dim3 grid(OUTF / (TPB * CPT), NGY + 1);  // (32, 33): 1024 main + 32 const blocks
    k_fused<<<grid, TPB>>>(x, qw, scales, zeros, bias, ow, oidx, out,
                           OUTF, INF, NOUT);
}